// round 5
// baseline (speedup 1.0000x reference)
#include <cuda_runtime.h>
#include <cuda_bf16.h>
#include <math.h>

#define Bb 4
#define Ss 4096
#define Hh 8
#define Dd 64
#define HD 512
#define NC 64
#define CS 64
#define BSn 16384
#define Mm 131072          // B*S*H rows
#define MD (Mm*64)         // 8.39M elems

// ---- fp32 scratch ----
__device__ float g_fg  [MD];
__device__ float g_igh [MD];
__device__ float g_ctot[Bb*NC*HD];
__device__ float g_a   [Bb*NC*HD];
__device__ float g_bv  [Bb*NC*HD];
__device__ float g_cellin[Bb*NC*HD];
// ---- bf16 hi/lo operand scratch ----
__device__ __nv_bfloat16 g_xh[MD], g_xl[MD];
__device__ __nv_bfloat16 g_lnh[MD], g_lnl[MD];
__device__ __nv_bfloat16 g_ch[MD], g_cl[MD];
__device__ __nv_bfloat16 g_W1h[192*128], g_W1l[192*128];   // [c][k], gate-remapped
__device__ __nv_bfloat16 g_W2h[64*128],  g_W2l[64*128];    // [n][k]

__device__ __forceinline__ float sigmf(float z){ return 1.f/(1.f+__expf(-z)); }

__device__ __forceinline__ void split_bf16(float v, __nv_bfloat16 &h, __nv_bfloat16 &l){
    h = __float2bfloat16(v);
    l = __float2bfloat16(v - __bfloat162float(h));
}

__device__ __forceinline__ void mma16(float* c, const unsigned* a, unsigned b0, unsigned b1){
    asm volatile("mma.sync.aligned.m16n8k16.row.col.f32.bf16.bf16.f32 "
        "{%0,%1,%2,%3}, {%4,%5,%6,%7}, {%8,%9}, {%0,%1,%2,%3};"
        : "+f"(c[0]),"+f"(c[1]),"+f"(c[2]),"+f"(c[3])
        : "r"(a[0]),"r"(a[1]),"r"(a[2]),"r"(a[3]), "r"(b0),"r"(b1));
}

// ---- P0: weight transpose + remap + split ----
__global__ void k_prepw(const float* __restrict__ W1, const float* __restrict__ W2){
    int c = blockIdx.x, k = threadIdx.x;
    if (c < 192){
        int wn=c/48, rem=c%48, gate=rem>>4, dd=rem&15;
        float v = W1[k*192 + gate*64 + wn*16 + dd];
        __nv_bfloat16 h,l; split_bf16(v,h,l);
        g_W1h[c*128+k]=h; g_W1l[c*128+k]=l;
    } else {
        int c2 = c-192;
        float v = W2[k*64 + c2];
        __nv_bfloat16 h,l; split_bf16(v,h,l);
        g_W2h[c2*128+k]=h; g_W2l[c2*128+k]=l;
    }
}

// ---- K1: per-chunk totals + x split to bf16 ----
__global__ void k_chunksum(const float* __restrict__ x){
    int bc = blockIdx.x; int b = bc>>6; int c = bc&63; int t = threadIdx.x;
    int base = (b*Ss + c*CS)*HD + t;
    float acc = 0.f;
    #pragma unroll 8
    for (int s=0;s<CS;s++){
        float v = x[base + s*HD];
        acc += v;
        __nv_bfloat16 h,l; split_bf16(v,h,l);
        g_xh[base+s*HD]=h; g_xl[base+s*HD]=l;
    }
    g_ctot[bc*HD + t] = acc;
}

// ---- K2: exclusive scan of chunk totals ----
__global__ void k_chunkscan(){
    int ch = blockIdx.x*blockDim.x + threadIdx.x;
    int b = ch>>9, t = ch&511;
    float run = 0.f;
    #pragma unroll
    for (int c=0;c<NC;c++){
        int i = (b*NC + c)*HD + t;
        float v = g_ctot[i]; g_ctot[i] = run; run += v;
    }
}

// ---- K3: fused cumsum + LN stats + normalize + bf16 split ----
// 128 threads per (b,chunk); thread owns 4 contiguous channels.
__global__ __launch_bounds__(128) void k_lnfused(
    const float* __restrict__ x, const float* __restrict__ gamma,
    const float* __restrict__ beta){
    __shared__ float r1[2][4], r2[2][4];
    int bc = blockIdx.x; int b = bc>>6; int c = bc&63; int t = threadIdx.x;
    int lane = t&31, wid = t>>5;
    int base = (b*Ss + c*CS)*HD + t*4;

    float4 gm = *(const float4*)(gamma + t*4);
    float4 bt = *(const float4*)(beta  + t*4);
    float4 run = *(const float4*)(g_ctot + bc*HD + t*4);
    float4 xv = *(const float4*)(x + base);

    for (int s=0;s<CS;s++){
        float4 xn;
        if (s+1 < CS) xn = *(const float4*)(x + base + (s+1)*HD);
        // stats over block of run
        float s1 = run.x+run.y+run.z+run.w;
        float s2 = run.x*run.x+run.y*run.y+run.z*run.z+run.w*run.w;
        #pragma unroll
        for (int o=16;o;o>>=1){
            s1 += __shfl_xor_sync(0xffffffffu, s1, o);
            s2 += __shfl_xor_sync(0xffffffffu, s2, o);
        }
        int par = s&1;
        if (lane==0){ r1[par][wid]=s1; r2[par][wid]=s2; }
        __syncthreads();
        s1 = r1[par][0]+r1[par][1]+r1[par][2]+r1[par][3];
        s2 = r2[par][0]+r2[par][1]+r2[par][2]+r2[par][3];
        float mean = s1*(1.f/512.f);
        float rinv = rsqrtf(s2*(1.f/512.f) - mean*mean + 1e-5f);
        float w0 = (run.x-mean)*rinv*gm.x + bt.x;
        float w1 = (run.y-mean)*rinv*gm.y + bt.y;
        float w2 = (run.z-mean)*rinv*gm.z + bt.z;
        float w3 = (run.w-mean)*rinv*gm.w + bt.w;
        __nv_bfloat16 h0,l0,h1,l1,h2,l2,h3,l3;
        split_bf16(w0,h0,l0); split_bf16(w1,h1,l1);
        split_bf16(w2,h2,l2); split_bf16(w3,h3,l3);
        __nv_bfloat162 ph0=__halves2bfloat162(h0,h1), ph1=__halves2bfloat162(h2,h3);
        __nv_bfloat162 pl0=__halves2bfloat162(l0,l1), pl1=__halves2bfloat162(l2,l3);
        uint2 uh; uh.x=*(unsigned*)&ph0; uh.y=*(unsigned*)&ph1;
        uint2 ul; ul.x=*(unsigned*)&pl0; ul.y=*(unsigned*)&pl1;
        *(uint2*)(g_lnh + base + s*HD) = uh;
        *(uint2*)(g_lnl + base + s*HD) = ul;
        run.x += xv.x; run.y += xv.y; run.z += xv.z; run.w += xv.w;
        xv = xn;
    }
}

// ---- K5: GEMM1 bf16-compensated mma, M64 x N192, fused gate epilogue ----
__global__ __launch_bounds__(256,2) void k_gemm1(const float* __restrict__ bias){
    __shared__ __nv_bfloat16 Ah[2][64*24], Al[2][64*24];
    __shared__ __nv_bfloat16 Bh[2][192*24], Bl[2][192*24];
    int t = threadIdx.x;
    int r0 = blockIdx.x*64;
    int lane=t&31, wid=t>>5, wm=wid&1, wn=wid>>1;
    int g=lane>>2, tg=lane&3;

    float Cr[2][6][4];
    #pragma unroll
    for (int a=0;a<2;a++)
        #pragma unroll
        for (int b=0;b<6;b++)
            #pragma unroll
            for (int c=0;c<4;c++) Cr[a][b][c]=0.f;

    unsigned ra_h[2], ra_l[2], rb_h[6], rb_l[6];

    auto load_stage = [&](int s){
        const unsigned* gah = (const unsigned*)(s<4 ? g_xh : g_lnh);
        const unsigned* gal = (const unsigned*)(s<4 ? g_xl : g_lnl);
        int so = (s&3)*8;
        #pragma unroll
        for (int i=0;i<2;i++){
            int idx = t + i*256, row = idx>>3, c8 = idx&7;
            int gi = (r0+row)*32 + so + c8;
            ra_h[i] = gah[gi]; ra_l[i] = gal[gi];
        }
        const unsigned* gbh = (const unsigned*)g_W1h;
        const unsigned* gbl = (const unsigned*)g_W1l;
        #pragma unroll
        for (int i=0;i<6;i++){
            int idx = t + i*256, row = idx>>3, c8 = idx&7;
            int gi = row*64 + s*8 + c8;
            rb_h[i] = gbh[gi]; rb_l[i] = gbl[gi];
        }
    };
    auto store_stage = [&](int buf){
        unsigned* sah = (unsigned*)Ah[buf]; unsigned* sal = (unsigned*)Al[buf];
        #pragma unroll
        for (int i=0;i<2;i++){
            int idx = t + i*256, row = idx>>3, c8 = idx&7;
            sah[row*12+c8] = ra_h[i]; sal[row*12+c8] = ra_l[i];
        }
        unsigned* sbh = (unsigned*)Bh[buf]; unsigned* sbl = (unsigned*)Bl[buf];
        #pragma unroll
        for (int i=0;i<6;i++){
            int idx = t + i*256, row = idx>>3, c8 = idx&7;
            sbh[row*12+c8] = rb_h[i]; sbl[row*12+c8] = rb_l[i];
        }
    };

    load_stage(0); store_stage(0); __syncthreads();
    for (int s=0;s<8;s++){
        int buf = s&1;
        if (s<7) load_stage(s+1);
        const unsigned* As_h = (const unsigned*)Ah[buf];
        const unsigned* As_l = (const unsigned*)Al[buf];
        const unsigned* Bs_h = (const unsigned*)Bh[buf];
        const unsigned* Bs_l = (const unsigned*)Bl[buf];
        unsigned ah[2][4], al[2][4];
        #pragma unroll
        for (int mf=0;mf<2;mf++){
            int mr = wm*32 + mf*16;
            ah[mf][0]=As_h[(mr+g  )*12+tg  ]; ah[mf][1]=As_h[(mr+g+8)*12+tg  ];
            ah[mf][2]=As_h[(mr+g  )*12+tg+4]; ah[mf][3]=As_h[(mr+g+8)*12+tg+4];
            al[mf][0]=As_l[(mr+g  )*12+tg  ]; al[mf][1]=As_l[(mr+g+8)*12+tg  ];
            al[mf][2]=As_l[(mr+g  )*12+tg+4]; al[mf][3]=As_l[(mr+g+8)*12+tg+4];
        }
        #pragma unroll
        for (int nf=0;nf<6;nf++){
            int cb = wn*48 + nf*8 + g;
            unsigned bh0=Bs_h[cb*12+tg], bh1=Bs_h[cb*12+tg+4];
            unsigned bl0=Bs_l[cb*12+tg], bl1=Bs_l[cb*12+tg+4];
            #pragma unroll
            for (int mf=0;mf<2;mf++){
                mma16(Cr[mf][nf], ah[mf], bh0, bh1);
                mma16(Cr[mf][nf], al[mf], bh0, bh1);
                mma16(Cr[mf][nf], ah[mf], bl0, bl1);
            }
        }
        if (s<7){ store_stage((s+1)&1); __syncthreads(); }
    }
    #pragma unroll
    for (int mf=0;mf<2;mf++)
        #pragma unroll
        for (int nfd=0;nfd<2;nfd++)
            #pragma unroll
            for (int j=0;j<4;j++){
                int row = r0 + wm*32 + mf*16 + g + ((j>>1)<<3);
                int d = wn*16 + nfd*8 + 2*tg + (j&1);
                float ig  = Cr[mf][nfd  ][j] + __ldg(&bias[d]);
                float fgv = Cr[mf][nfd+2][j] + __ldg(&bias[64+d]);
                float hd  = Cr[mf][nfd+4][j] + __ldg(&bias[128+d]);
                g_fg [row*64+d] = sigmf(fgv);
                g_igh[row*64+d] = sigmf(ig)*fmaxf(hd,0.f);
            }
}

// ---- K6: per-chunk affine scan coefficients ----
__global__ void k_seg_ab(){
    int bc = blockIdx.x; int t = threadIdx.x;
    int b = bc>>6, c = bc&63;
    int base = (b*Ss + c*CS)*HD + t;
    float a = 1.f, bb2 = 0.f;
    #pragma unroll 8
    for (int s=0;s<CS;s++){
        float f = g_fg[base + s*HD];
        float gg = g_igh[base + s*HD];
        a *= f; bb2 = bb2*f + gg;
    }
    g_a[bc*HD + t] = a; g_bv[bc*HD + t] = bb2;
}

// ---- K7: chunk-carry scan ----
__global__ void k_carry(const float* __restrict__ initcx){
    int ch = blockIdx.x*blockDim.x + threadIdx.x;
    int b = ch>>9, t = ch&511;
    float cell = initcx[t];
    #pragma unroll
    for (int c=0;c<NC;c++){
        int i = (b*NC + c)*HD + t;
        g_cellin[i] = cell;
        cell = g_a[i]*cell + g_bv[i];
    }
}

// ---- K8: in-chunk cell recurrence -> bf16 hi/lo only ----
__global__ void k_cell(){
    int bc = blockIdx.x; int t = threadIdx.x;
    int b = bc>>6, c = bc&63;
    int base = (b*Ss + c*CS)*HD + t;
    float cell = g_cellin[bc*HD + t];
    #pragma unroll 8
    for (int s=0;s<CS;s++){
        cell = g_fg[base + s*HD]*cell + g_igh[base + s*HD];
        __nv_bfloat16 h,l; split_bf16(cell,h,l);
        g_ch[base+s*HD]=h; g_cl[base+s*HD]=l;
    }
}

// ---- K9: GEMM2 bf16-compensated mma, fused og*cell (cell = hi+lo) ----
__global__ __launch_bounds__(256,2) void k_gemm2(const float* __restrict__ bias,
                                                 float* __restrict__ out){
    __shared__ __nv_bfloat16 Ah[2][64*24], Al[2][64*24];
    __shared__ __nv_bfloat16 Bh[2][64*24], Bl[2][64*24];
    int t = threadIdx.x;
    int r0 = blockIdx.x*64;
    int lane=t&31, wid=t>>5, wm=wid&1, wn=wid>>1;
    int g=lane>>2, tg=lane&3;

    float Cr[2][2][4];
    #pragma unroll
    for (int a=0;a<2;a++)
        #pragma unroll
        for (int b=0;b<2;b++)
            #pragma unroll
            for (int c=0;c<4;c++) Cr[a][b][c]=0.f;

    unsigned ra_h[2], ra_l[2], rb_h[2], rb_l[2];
    auto load_stage = [&](int s){
        const unsigned* gah = (const unsigned*)(s<4 ? g_xh : g_ch);
        const unsigned* gal = (const unsigned*)(s<4 ? g_xl : g_cl);
        int so = (s&3)*8;
        #pragma unroll
        for (int i=0;i<2;i++){
            int idx = t + i*256, row = idx>>3, c8 = idx&7;
            int gi = (r0+row)*32 + so + c8;
            ra_h[i] = gah[gi]; ra_l[i] = gal[gi];
        }
        const unsigned* gbh = (const unsigned*)g_W2h;
        const unsigned* gbl = (const unsigned*)g_W2l;
        #pragma unroll
        for (int i=0;i<2;i++){
            int idx = t + i*256, row = idx>>3, c8 = idx&7;
            int gi = row*64 + s*8 + c8;
            rb_h[i] = gbh[gi]; rb_l[i] = gbl[gi];
        }
    };
    auto store_stage = [&](int buf){
        unsigned* sah=(unsigned*)Ah[buf]; unsigned* sal=(unsigned*)Al[buf];
        unsigned* sbh=(unsigned*)Bh[buf]; unsigned* sbl=(unsigned*)Bl[buf];
        #pragma unroll
        for (int i=0;i<2;i++){
            int idx = t + i*256, row = idx>>3, c8 = idx&7;
            sah[row*12+c8]=ra_h[i]; sal[row*12+c8]=ra_l[i];
            sbh[row*12+c8]=rb_h[i]; sbl[row*12+c8]=rb_l[i];
        }
    };

    load_stage(0); store_stage(0); __syncthreads();
    for (int s=0;s<8;s++){
        int buf = s&1;
        if (s<7) load_stage(s+1);
        const unsigned* As_h=(const unsigned*)Ah[buf];
        const unsigned* As_l=(const unsigned*)Al[buf];
        const unsigned* Bs_h=(const unsigned*)Bh[buf];
        const unsigned* Bs_l=(const unsigned*)Bl[buf];
        unsigned ah[2][4], al[2][4];
        #pragma unroll
        for (int mf=0;mf<2;mf++){
            int mr = wm*32 + mf*16;
            ah[mf][0]=As_h[(mr+g  )*12+tg  ]; ah[mf][1]=As_h[(mr+g+8)*12+tg  ];
            ah[mf][2]=As_h[(mr+g  )*12+tg+4]; ah[mf][3]=As_h[(mr+g+8)*12+tg+4];
            al[mf][0]=As_l[(mr+g  )*12+tg  ]; al[mf][1]=As_l[(mr+g+8)*12+tg  ];
            al[mf][2]=As_l[(mr+g  )*12+tg+4]; al[mf][3]=As_l[(mr+g+8)*12+tg+4];
        }
        #pragma unroll
        for (int nf=0;nf<2;nf++){
            int cb = wn*16 + nf*8 + g;
            unsigned bh0=Bs_h[cb*12+tg], bh1=Bs_h[cb*12+tg+4];
            unsigned bl0=Bs_l[cb*12+tg], bl1=Bs_l[cb*12+tg+4];
            #pragma unroll
            for (int mf=0;mf<2;mf++){
                mma16(Cr[mf][nf], ah[mf], bh0, bh1);
                mma16(Cr[mf][nf], al[mf], bh0, bh1);
                mma16(Cr[mf][nf], ah[mf], bl0, bl1);
            }
        }
        if (s<7){ store_stage((s+1)&1); __syncthreads(); }
    }
    #pragma unroll
    for (int mf=0;mf<2;mf++)
        #pragma unroll
        for (int nf=0;nf<2;nf++)
            #pragma unroll
            for (int j=0;j<4;j++){
                int row = r0 + wm*32 + mf*16 + g + ((j>>1)<<3);
                int col = wn*16 + nf*8 + 2*tg + (j&1);
                float og = sigmf(Cr[mf][nf][j] + __ldg(&bias[col]));
                float cell = __bfloat162float(g_ch[row*64+col]) +
                             __bfloat162float(g_cl[row*64+col]);
                out[row*64+col] = og * cell;
            }
}

extern "C" void kernel_launch(void* const* d_in, const int* in_sizes, int n_in,
                              void* d_out, int out_size){
    const float* x      = (const float*)d_in[0];
    const float* W_hid  = (const float*)d_in[1];
    const float* b_hid  = (const float*)d_in[2];
    const float* W_og   = (const float*)d_in[3];
    const float* b_og   = (const float*)d_in[4];
    const float* gamma  = (const float*)d_in[5];
    const float* beta   = (const float*)d_in[6];
    const float* initcx = (const float*)d_in[7];
    float* out = (float*)d_out;

    k_prepw    <<<256, 128>>>(W_hid, W_og);
    k_chunksum <<<Bb*NC, 512>>>(x);
    k_chunkscan<<<16, 128>>>();
    k_lnfused  <<<Bb*NC, 128>>>(x, gamma, beta);
    k_gemm1    <<<Mm/64, 256>>>(b_hid);
    k_seg_ab   <<<Bb*NC, 512>>>();
    k_carry    <<<16, 128>>>(initcx);
    k_cell     <<<Bb*NC, 512>>>();
    k_gemm2    <<<Mm/64, 256>>>(b_og, out);
}